// round 2
// baseline (speedup 1.0000x reference)
#include <cuda_runtime.h>
#include <cuda_bf16.h>

#define BB 16
#define TT 8192
#define DD 256
#define MAXSEG 4096
#define LN_EPS 1e-5f

// Scratch (static device globals; no runtime allocation)
__device__ float g_means[(size_t)BB * MAXSEG * DD];   // 64 MB compact pooled means
__device__ int   g_seg_start[BB * MAXSEG];
__device__ int   g_seg_end[BB * MAXSEG];
__device__ int   g_nsegs[BB];
__device__ float g_Wt[DD * DD];                        // W transposed: Wt[d][e] = W[e][d]
__device__ float g_empty[DD];                          // LN(b_proj)*gamma+beta for empty slots
__device__ int   g_id_stride;                          // 1 = int32 ids, 2 = int64 ids

// ---------------------------------------------------------------------------
// Kernel -1: detect whether input_ids buffer is int32 or int64.
// For int64 values in [0,8), every odd int32 word (high word) is 0.
// For random int32 values in [0,8), P(256 odd words all zero) = 8^-256 ~ 0.
// ---------------------------------------------------------------------------
__global__ void k_detect(const int* __restrict__ ids32) {
    __shared__ int any;
    if (threadIdx.x == 0) any = 0;
    __syncthreads();
    // check odd words 1,3,...,511 (256 words) with 256 threads
    if (ids32[2 * threadIdx.x + 1] != 0) atomicOr(&any, 1);
    __syncthreads();
    if (threadIdx.x == 0) g_id_stride = any ? 1 : 2;
}

__device__ __forceinline__ int load_id(const int* ids32, int stride, int b, int t) {
    return ids32[(size_t)(b * TT + t) * stride];
}

// ---------------------------------------------------------------------------
// Kernel 0: prep — empty vector (LN of b_proj) + W transpose
// ---------------------------------------------------------------------------
__global__ void k_prep(const float* __restrict__ W, const float* __restrict__ bp,
                       const float* __restrict__ gamma, const float* __restrict__ beta) {
    int tid = threadIdx.x;  // 256 threads
    __shared__ float red[256];
    float v = bp[tid];
    red[tid] = v;
    __syncthreads();
    for (int s = 128; s > 0; s >>= 1) {
        if (tid < s) red[tid] += red[tid + s];
        __syncthreads();
    }
    float mu = red[0] * (1.0f / DD);
    __syncthreads();
    float d = v - mu;
    red[tid] = d * d;
    __syncthreads();
    for (int s = 128; s > 0; s >>= 1) {
        if (tid < s) red[tid] += red[tid + s];
        __syncthreads();
    }
    float var = red[0] * (1.0f / DD);
    g_empty[tid] = d * rsqrtf(var + LN_EPS) * gamma[tid] + beta[tid];

    // Transpose W: Wt[d][e] = W[e][d]. Reads coalesced per iteration.
    for (int e = 0; e < DD; e++)
        g_Wt[tid * DD + e] = W[e * DD + tid];
}

// ---------------------------------------------------------------------------
// Kernel 1: segmentation — per batch row, find maximal non-boundary runs
// ---------------------------------------------------------------------------
__global__ void k_seg(const int* __restrict__ ids) {
    int b = blockIdx.x;
    int stride = g_id_stride;
    __shared__ int ss[257], se[257];
    int tid = threadIdx.x;           // 256 threads x 32 tokens
    int base = tid * 32;

    int cs = 0, ce = 0;
    bool prevb = (base == 0) || (load_id(ids, stride, b, base - 1) == 0);
    #pragma unroll
    for (int i = 0; i < 32; i++) {
        int t = base + i;
        bool isb = (load_id(ids, stride, b, t) == 0);
        bool nextb = (t == TT - 1) || (load_id(ids, stride, b, t + 1) == 0);
        cs += (!isb && prevb) ? 1 : 0;
        ce += (!isb && nextb) ? 1 : 0;
        prevb = isb;
    }
    ss[tid] = cs;
    se[tid] = ce;
    __syncthreads();
    if (tid == 0) {
        int a = 0, c2 = 0;
        for (int i = 0; i < 256; i++) {
            int t1 = ss[i]; ss[i] = a; a += t1;
            int t2 = se[i]; se[i] = c2; c2 += t2;
        }
        g_nsegs[b] = a;
    }
    __syncthreads();
    int so = ss[tid], eo = se[tid];
    prevb = (base == 0) || (load_id(ids, stride, b, base - 1) == 0);
    #pragma unroll
    for (int i = 0; i < 32; i++) {
        int t = base + i;
        bool isb = (load_id(ids, stride, b, t) == 0);
        bool nextb = (t == TT - 1) || (load_id(ids, stride, b, t + 1) == 0);
        if (!isb && prevb) g_seg_start[b * MAXSEG + (so++)] = t;
        if (!isb && nextb) g_seg_end[b * MAXSEG + (eo++)] = t;
        prevb = isb;
    }
}

// ---------------------------------------------------------------------------
// Kernel 2: fill empty output rows with g_empty, and write mask
// One warp per output row; grid covers all B*T rows.
// ---------------------------------------------------------------------------
__global__ void k_fill(float* __restrict__ out, float* __restrict__ mask) {
    int row = blockIdx.x * 8 + (threadIdx.x >> 5);
    int lane = threadIdx.x & 31;
    int b = row >> 13;          // /8192
    int w = row & (TT - 1);
    int ns = g_nsegs[b];
    if (lane == 0) mask[row] = (w < ns) ? 1.0f : 0.0f;
    if (w < ns) return;         // active rows written by GEMM kernel
    float4 e0 = *(const float4*)(g_empty + lane * 4);
    float4 e1 = *(const float4*)(g_empty + 128 + lane * 4);
    float4* o = (float4*)(out + (size_t)row * DD);
    o[lane] = e0;
    o[32 + lane] = e1;
}

// ---------------------------------------------------------------------------
// Kernel 3: pooling — one warp per segment, mean over its contiguous run
// ---------------------------------------------------------------------------
__global__ void k_pool(const float* __restrict__ x) {
    int b = blockIdx.x;
    int warp = threadIdx.x >> 5;
    int lane = threadIdx.x & 31;
    int w = blockIdx.y * 8 + warp;
    int ns = g_nsegs[b];
    if (w >= ns) return;
    int s = g_seg_start[b * MAXSEG + w];
    int e = g_seg_end[b * MAXSEG + w];
    float4 a0 = make_float4(0.f, 0.f, 0.f, 0.f);
    float4 a1 = make_float4(0.f, 0.f, 0.f, 0.f);
    const float* xb = x + (size_t)b * TT * DD;
    for (int t = s; t <= e; t++) {
        const float4* p = (const float4*)(xb + (size_t)t * DD);
        float4 v0 = p[lane];
        float4 v1 = p[32 + lane];
        a0.x += v0.x; a0.y += v0.y; a0.z += v0.z; a0.w += v0.w;
        a1.x += v1.x; a1.y += v1.y; a1.z += v1.z; a1.w += v1.w;
    }
    float inv = 1.0f / (float)(e - s + 1);
    a0.x *= inv; a0.y *= inv; a0.z *= inv; a0.w *= inv;
    a1.x *= inv; a1.y *= inv; a1.z *= inv; a1.w *= inv;
    float4* m = (float4*)(g_means + (size_t)(b * MAXSEG + w) * DD);
    m[lane] = a0;
    m[32 + lane] = a1;
}

// ---------------------------------------------------------------------------
// Kernel 4: GEMM (means @ W^T + b) fused with LayerNorm, scatter to output
// Tile: BM=32 rows x BN=256 cols (full row in block -> LN in-register via warp)
// 256 threads: warp tm owns rows [tm*4, tm*4+4), lane tn owns cols [tn*8, +8)
// ---------------------------------------------------------------------------
__global__ void __launch_bounds__(256) k_gemm(const float* __restrict__ bproj,
                                              const float* __restrict__ gamma,
                                              const float* __restrict__ beta,
                                              float* __restrict__ out) {
    int b = blockIdx.x;
    int m0 = blockIdx.y * 32;
    int ns = g_nsegs[b];
    if (m0 >= ns) return;
    int active = min(32, ns - m0);

    __shared__ float As[32][36];     // [k][m], padded for 16B-aligned float4
    __shared__ float Bs[32][256];    // [k][n]

    int tid = threadIdx.x;
    int tm = tid >> 5;   // warp id = row group
    int tn = tid & 31;   // lane = col group

    float c[4][8];
    #pragma unroll
    for (int r = 0; r < 4; r++)
        #pragma unroll
        for (int j = 0; j < 8; j++) c[r][j] = 0.f;

    const float* Arow = g_means + (size_t)(b * MAXSEG + m0) * DD;

    for (int kt = 0; kt < 8; kt++) {
        // Load A tile 32x32 (transposed into As[k][m]); zero rows beyond active
        {
            int m = tid >> 3, kq = tid & 7;
            float4 v = make_float4(0.f, 0.f, 0.f, 0.f);
            if (m < active)
                v = *(const float4*)(Arow + (size_t)m * DD + kt * 32 + kq * 4);
            As[kq * 4 + 0][m] = v.x;
            As[kq * 4 + 1][m] = v.y;
            As[kq * 4 + 2][m] = v.z;
            As[kq * 4 + 3][m] = v.w;
        }
        // Load B tile 32x256 from Wt (contiguous, conflict-free STS.128)
        #pragma unroll
        for (int i = 0; i < 8; i++) {
            int f = tid + i * 256;
            int k = f >> 6, n4 = f & 63;
            *(float4*)&Bs[k][n4 * 4] =
                *(const float4*)(g_Wt + (size_t)(kt * 32 + k) * DD + n4 * 4);
        }
        __syncthreads();
        #pragma unroll
        for (int kk = 0; kk < 32; kk++) {
            float4 a  = *(float4*)&As[kk][tm * 4];          // broadcast within warp
            float4 b0 = *(float4*)&Bs[kk][tn * 8];
            float4 b1 = *(float4*)&Bs[kk][tn * 8 + 4];
            float av[4] = {a.x, a.y, a.z, a.w};
            float bv[8] = {b0.x, b0.y, b0.z, b0.w, b1.x, b1.y, b1.z, b1.w};
            #pragma unroll
            for (int r = 0; r < 4; r++)
                #pragma unroll
                for (int j = 0; j < 8; j++)
                    c[r][j] = fmaf(av[r], bv[j], c[r][j]);
        }
        __syncthreads();
    }

    // Epilogue: + b_proj, LayerNorm per row (row lives entirely in one warp)
    float bp[8], gm[8], bt[8];
    {
        float4 t0 = *(const float4*)(bproj + tn * 8);
        float4 t1 = *(const float4*)(bproj + tn * 8 + 4);
        bp[0]=t0.x; bp[1]=t0.y; bp[2]=t0.z; bp[3]=t0.w; bp[4]=t1.x; bp[5]=t1.y; bp[6]=t1.z; bp[7]=t1.w;
        t0 = *(const float4*)(gamma + tn * 8);
        t1 = *(const float4*)(gamma + tn * 8 + 4);
        gm[0]=t0.x; gm[1]=t0.y; gm[2]=t0.z; gm[3]=t0.w; gm[4]=t1.x; gm[5]=t1.y; gm[6]=t1.z; gm[7]=t1.w;
        t0 = *(const float4*)(beta + tn * 8);
        t1 = *(const float4*)(beta + tn * 8 + 4);
        bt[0]=t0.x; bt[1]=t0.y; bt[2]=t0.z; bt[3]=t0.w; bt[4]=t1.x; bt[5]=t1.y; bt[6]=t1.z; bt[7]=t1.w;
    }

    #pragma unroll
    for (int r = 0; r < 4; r++) {
        int w = m0 + tm * 4 + r;
        if (w >= ns) continue;   // uniform across warp (depends only on tm,r)
        float s = 0.f, q = 0.f;
        #pragma unroll
        for (int j = 0; j < 8; j++) {
            float val = c[r][j] + bp[j];
            c[r][j] = val;
            s += val;
            q += val * val;
        }
        #pragma unroll
        for (int off = 16; off > 0; off >>= 1) {
            s += __shfl_xor_sync(0xFFFFFFFFu, s, off);
            q += __shfl_xor_sync(0xFFFFFFFFu, q, off);
        }
        float mu = s * (1.0f / DD);
        float var = q * (1.0f / DD) - mu * mu;
        float rstd = rsqrtf(var + LN_EPS);
        float o[8];
        #pragma unroll
        for (int j = 0; j < 8; j++)
            o[j] = (c[r][j] - mu) * rstd * gm[j] + bt[j];
        float* orow = out + (size_t)(b * TT + w) * DD + tn * 8;
        *(float4*)(orow)     = make_float4(o[0], o[1], o[2], o[3]);
        *(float4*)(orow + 4) = make_float4(o[4], o[5], o[6], o[7]);
    }
}

// ---------------------------------------------------------------------------
extern "C" void kernel_launch(void* const* d_in, const int* in_sizes, int n_in,
                              void* d_out, int out_size) {
    const float* x     = (const float*)d_in[0];
    const int*   ids   = (const int*)d_in[1];   // int32 or int64 (detected on device)
    const float* W     = (const float*)d_in[2];
    const float* bproj = (const float*)d_in[3];
    const float* gamma = (const float*)d_in[4];
    const float* beta  = (const float*)d_in[5];
    float* out  = (float*)d_out;
    float* mask = out + (size_t)BB * TT * DD;

    k_detect<<<1, 256>>>(ids);
    k_prep<<<1, 256>>>(W, bproj, gamma, beta);
    k_seg<<<BB, 256>>>(ids);
    k_fill<<<(BB * TT) / 8, 256>>>(out, mask);
    k_pool<<<dim3(BB, MAXSEG / 8), 256>>>(x);
    k_gemm<<<dim3(BB, MAXSEG / 32), 256>>>(bproj, gamma, beta, out);
}

// round 3
// speedup vs baseline: 1.8854x; 1.8854x over previous
#include <cuda_runtime.h>
#include <cuda_bf16.h>

#define BB 16
#define TT 8192
#define DD 256
#define MAXSEG 4096
#define LN_EPS 1e-5f

// Scratch (static device globals; no runtime allocation)
__device__ float g_means[(size_t)BB * MAXSEG * DD];   // 64 MB compact pooled means
__device__ int   g_seg_start[BB * MAXSEG];
__device__ int   g_seg_end[BB * MAXSEG];
__device__ int   g_nsegs[BB];
__device__ float g_empty[DD];                          // LN(b_proj)*gamma+beta for empty slots
__device__ int   g_id_stride;                          // 1 = int32 ids, 2 = int64 ids

// ---------------------------------------------------------------------------
// Kernel -1: detect whether input_ids buffer is int32 or int64.
// ---------------------------------------------------------------------------
__global__ void k_detect(const int* __restrict__ ids32) {
    __shared__ int any;
    if (threadIdx.x == 0) any = 0;
    __syncthreads();
    if (ids32[2 * threadIdx.x + 1] != 0) atomicOr(&any, 1);
    __syncthreads();
    if (threadIdx.x == 0) g_id_stride = any ? 1 : 2;
}

__device__ __forceinline__ int load_id(const int* ids32, int stride, int b, int t) {
    return ids32[(size_t)(b * TT + t) * stride];
}

// ---------------------------------------------------------------------------
// Kernel 0: prep — empty vector (LN of b_proj)   [transpose removed]
// ---------------------------------------------------------------------------
__global__ void k_prep(const float* __restrict__ bp,
                       const float* __restrict__ gamma, const float* __restrict__ beta) {
    int tid = threadIdx.x;  // 256 threads
    __shared__ float red[256];
    float v = bp[tid];
    red[tid] = v;
    __syncthreads();
    for (int s = 128; s > 0; s >>= 1) {
        if (tid < s) red[tid] += red[tid + s];
        __syncthreads();
    }
    float mu = red[0] * (1.0f / DD);
    __syncthreads();
    float d = v - mu;
    red[tid] = d * d;
    __syncthreads();
    for (int s = 128; s > 0; s >>= 1) {
        if (tid < s) red[tid] += red[tid + s];
        __syncthreads();
    }
    float var = red[0] * (1.0f / DD);
    g_empty[tid] = d * rsqrtf(var + LN_EPS) * gamma[tid] + beta[tid];
}

// ---------------------------------------------------------------------------
// Kernel 1: segmentation — per batch row, find maximal non-boundary runs
// ---------------------------------------------------------------------------
__global__ void k_seg(const int* __restrict__ ids) {
    int b = blockIdx.x;
    int stride = g_id_stride;
    __shared__ int ss[257], se[257];
    int tid = threadIdx.x;           // 256 threads x 32 tokens
    int base = tid * 32;

    int cs = 0, ce = 0;
    bool prevb = (base == 0) || (load_id(ids, stride, b, base - 1) == 0);
    #pragma unroll
    for (int i = 0; i < 32; i++) {
        int t = base + i;
        bool isb = (load_id(ids, stride, b, t) == 0);
        bool nextb = (t == TT - 1) || (load_id(ids, stride, b, t + 1) == 0);
        cs += (!isb && prevb) ? 1 : 0;
        ce += (!isb && nextb) ? 1 : 0;
        prevb = isb;
    }
    ss[tid] = cs;
    se[tid] = ce;
    __syncthreads();
    if (tid == 0) {
        int a = 0, c2 = 0;
        for (int i = 0; i < 256; i++) {
            int t1 = ss[i]; ss[i] = a; a += t1;
            int t2 = se[i]; se[i] = c2; c2 += t2;
        }
        g_nsegs[b] = a;
    }
    __syncthreads();
    int so = ss[tid], eo = se[tid];
    prevb = (base == 0) || (load_id(ids, stride, b, base - 1) == 0);
    #pragma unroll
    for (int i = 0; i < 32; i++) {
        int t = base + i;
        bool isb = (load_id(ids, stride, b, t) == 0);
        bool nextb = (t == TT - 1) || (load_id(ids, stride, b, t + 1) == 0);
        if (!isb && prevb) g_seg_start[b * MAXSEG + (so++)] = t;
        if (!isb && nextb) g_seg_end[b * MAXSEG + (eo++)] = t;
        prevb = isb;
    }
}

// ---------------------------------------------------------------------------
// Kernel 2: fill empty output rows + mask. 4 rows per warp, empty vec in regs.
// ---------------------------------------------------------------------------
__global__ void k_fill(float* __restrict__ out, float* __restrict__ mask) {
    int warp = threadIdx.x >> 5, lane = threadIdx.x & 31;
    int row0 = blockIdx.x * 32 + warp * 4;
    int b = row0 >> 13;                       // all 4 rows share batch (32-aligned)
    int ns = g_nsegs[b];
    int w0 = row0 & (TT - 1);
    if (lane == 0) {
        float4 mv;
        mv.x = (w0 + 0 < ns) ? 1.0f : 0.0f;
        mv.y = (w0 + 1 < ns) ? 1.0f : 0.0f;
        mv.z = (w0 + 2 < ns) ? 1.0f : 0.0f;
        mv.w = (w0 + 3 < ns) ? 1.0f : 0.0f;
        *(float4*)(mask + row0) = mv;
    }
    if (w0 + 3 < ns) return;                  // all active
    float4 e0 = *(const float4*)(g_empty + lane * 4);
    float4 e1 = *(const float4*)(g_empty + 128 + lane * 4);
    #pragma unroll
    for (int i = 0; i < 4; i++) {
        if (w0 + i < ns) continue;
        float4* o = (float4*)(out + (size_t)(row0 + i) * DD);
        o[lane] = e0;
        o[32 + lane] = e1;
    }
}

// ---------------------------------------------------------------------------
// Kernel 3: pooling — one warp per segment, mean over its contiguous run
// ---------------------------------------------------------------------------
__global__ void k_pool(const float* __restrict__ x) {
    int b = blockIdx.x;
    int warp = threadIdx.x >> 5;
    int lane = threadIdx.x & 31;
    int w = blockIdx.y * 8 + warp;
    int ns = g_nsegs[b];
    if (w >= ns) return;
    int s = g_seg_start[b * MAXSEG + w];
    int e = g_seg_end[b * MAXSEG + w];
    float4 a0 = make_float4(0.f, 0.f, 0.f, 0.f);
    float4 a1 = make_float4(0.f, 0.f, 0.f, 0.f);
    const float* xb = x + (size_t)b * TT * DD;
    #pragma unroll 2
    for (int t = s; t <= e; t++) {
        const float4* p = (const float4*)(xb + (size_t)t * DD);
        float4 v0 = p[lane];
        float4 v1 = p[32 + lane];
        a0.x += v0.x; a0.y += v0.y; a0.z += v0.z; a0.w += v0.w;
        a1.x += v1.x; a1.y += v1.y; a1.z += v1.z; a1.w += v1.w;
    }
    float inv = 1.0f / (float)(e - s + 1);
    a0.x *= inv; a0.y *= inv; a0.z *= inv; a0.w *= inv;
    a1.x *= inv; a1.y *= inv; a1.z *= inv; a1.w *= inv;
    float4* m = (float4*)(g_means + (size_t)(b * MAXSEG + w) * DD);
    m[lane] = a0;
    m[32 + lane] = a1;
}

// ---------------------------------------------------------------------------
// Kernel 4: tf32 tensor-core GEMM (means @ W^T + b) fused with LayerNorm.
// Block: 32 rows x 256 cols. 8 warps as 2 (m16) x 4 (n64). mma.m16n8k8.tf32.
// W consumed directly as col-major B operand (W[n][k]) — no transpose needed.
// ---------------------------------------------------------------------------
__device__ __forceinline__ unsigned f2tf(float f) {
    unsigned u;
    asm("cvt.rna.tf32.f32 %0, %1;" : "=r"(u) : "f"(f));
    return u;
}

__global__ void __launch_bounds__(256) k_gemm(const float* __restrict__ W,
                                              const float* __restrict__ bproj,
                                              const float* __restrict__ gamma,
                                              const float* __restrict__ beta,
                                              float* __restrict__ out) {
    int b = blockIdx.x;
    int m0 = blockIdx.y * 32;
    int ns = g_nsegs[b];
    if (m0 >= ns) return;
    int active = min(32, ns - m0);

    __shared__ unsigned As[32][36];    // [m][k] tf32 chunk (pad: bank-conflict-free frags)
    __shared__ unsigned Bs[256][36];   // [n][k] tf32 chunk
    __shared__ float bpS[256], gmS[256], btS[256];
    __shared__ float rowsum[32][4];    // per (row, warp-col) partial sums
    __shared__ float rowsq[32][4];

    int tid = threadIdx.x;
    int warp = tid >> 5, lane = tid & 31;
    int wr = warp & 1;        // m-tile: wr*16
    int wc = warp >> 1;       // n-tile: wc*64
    int gid = lane >> 2, tig = lane & 3;

    bpS[tid] = bproj[tid];
    gmS[tid] = gamma[tid];
    btS[tid] = beta[tid];

    float c[8][4];
    #pragma unroll
    for (int nt = 0; nt < 8; nt++)
        #pragma unroll
        for (int j = 0; j < 4; j++) c[nt][j] = 0.f;

    const float* Abase = g_means + (size_t)(b * MAXSEG + m0) * DD;
    int lm = tid >> 3;              // 0..31
    int kq = (tid & 7) * 4;         // 0..28

    for (int kt = 0; kt < 8; kt++) {
        int k0 = kt * 32;
        // A chunk 32x32
        {
            float4 v = make_float4(0.f, 0.f, 0.f, 0.f);
            if (lm < active)
                v = *(const float4*)(Abase + (size_t)lm * DD + k0 + kq);
            As[lm][kq + 0] = f2tf(v.x);
            As[lm][kq + 1] = f2tf(v.y);
            As[lm][kq + 2] = f2tf(v.z);
            As[lm][kq + 3] = f2tf(v.w);
        }
        // B chunk 256x32 from W (rows of W, 32-float slice; coalesced 128B groups)
        #pragma unroll
        for (int p = 0; p < 8; p++) {
            int e = p * 32 + lm;
            float4 v = *(const float4*)(W + (size_t)e * DD + k0 + kq);
            Bs[e][kq + 0] = f2tf(v.x);
            Bs[e][kq + 1] = f2tf(v.y);
            Bs[e][kq + 2] = f2tf(v.z);
            Bs[e][kq + 3] = f2tf(v.w);
        }
        __syncthreads();
        #pragma unroll
        for (int ks = 0; ks < 4; ks++) {
            int kk = ks * 8;
            unsigned a0 = As[wr * 16 + gid][kk + tig];
            unsigned a1 = As[wr * 16 + gid + 8][kk + tig];
            unsigned a2 = As[wr * 16 + gid][kk + tig + 4];
            unsigned a3 = As[wr * 16 + gid + 8][kk + tig + 4];
            #pragma unroll
            for (int nt = 0; nt < 8; nt++) {
                int n = wc * 64 + nt * 8;
                unsigned b0 = Bs[n + gid][kk + tig];
                unsigned b1 = Bs[n + gid][kk + tig + 4];
                asm volatile(
                    "mma.sync.aligned.m16n8k8.row.col.f32.tf32.tf32.f32 "
                    "{%0,%1,%2,%3}, {%4,%5,%6,%7}, {%8,%9}, {%0,%1,%2,%3};"
                    : "+f"(c[nt][0]), "+f"(c[nt][1]), "+f"(c[nt][2]), "+f"(c[nt][3])
                    : "r"(a0), "r"(a1), "r"(a2), "r"(a3), "r"(b0), "r"(b1));
            }
        }
        __syncthreads();
    }

    // Epilogue: + bias, then row-wise LN. C element (nt, j): row = wr*16+gid (+8 if j>=2),
    // col = wc*64 + nt*8 + 2*tig + (j&1).
    float s0 = 0.f, q0 = 0.f, s1 = 0.f, q1 = 0.f;
    #pragma unroll
    for (int nt = 0; nt < 8; nt++) {
        int col = wc * 64 + nt * 8 + 2 * tig;
        float b0v = bpS[col], b1v = bpS[col + 1];
        c[nt][0] += b0v; c[nt][1] += b1v;
        c[nt][2] += b0v; c[nt][3] += b1v;
        s0 += c[nt][0] + c[nt][1];
        q0 += c[nt][0] * c[nt][0] + c[nt][1] * c[nt][1];
        s1 += c[nt][2] + c[nt][3];
        q1 += c[nt][2] * c[nt][2] + c[nt][3] * c[nt][3];
    }
    // reduce over tig (lanes differing in bits 0..1)
    #pragma unroll
    for (int off = 1; off <= 2; off <<= 1) {
        s0 += __shfl_xor_sync(0xFFFFFFFFu, s0, off);
        q0 += __shfl_xor_sync(0xFFFFFFFFu, q0, off);
        s1 += __shfl_xor_sync(0xFFFFFFFFu, s1, off);
        q1 += __shfl_xor_sync(0xFFFFFFFFu, q1, off);
    }
    if (tig == 0) {
        rowsum[wr * 16 + gid][wc] = s0;
        rowsq [wr * 16 + gid][wc] = q0;
        rowsum[wr * 16 + gid + 8][wc] = s1;
        rowsq [wr * 16 + gid + 8][wc] = q1;
    }
    __syncthreads();

    int r0 = wr * 16 + gid, r1 = r0 + 8;
    float sum0 = rowsum[r0][0] + rowsum[r0][1] + rowsum[r0][2] + rowsum[r0][3];
    float sq0  = rowsq [r0][0] + rowsq [r0][1] + rowsq [r0][2] + rowsq [r0][3];
    float sum1 = rowsum[r1][0] + rowsum[r1][1] + rowsum[r1][2] + rowsum[r1][3];
    float sq1  = rowsq [r1][0] + rowsq [r1][1] + rowsq [r1][2] + rowsq [r1][3];
    float mu0 = sum0 * (1.0f / DD);
    float mu1 = sum1 * (1.0f / DD);
    float rstd0 = rsqrtf(sq0 * (1.0f / DD) - mu0 * mu0 + LN_EPS);
    float rstd1 = rsqrtf(sq1 * (1.0f / DD) - mu1 * mu1 + LN_EPS);

    bool act0 = (m0 + r0) < ns;
    bool act1 = (m0 + r1) < ns;
    float* out0 = out + (size_t)(b * TT + m0 + r0) * DD;
    float* out1 = out + (size_t)(b * TT + m0 + r1) * DD;
    #pragma unroll
    for (int nt = 0; nt < 8; nt++) {
        int col = wc * 64 + nt * 8 + 2 * tig;
        float g0 = gmS[col], g1 = gmS[col + 1];
        float t0 = btS[col], t1 = btS[col + 1];
        if (act0) {
            float2 o;
            o.x = (c[nt][0] - mu0) * rstd0 * g0 + t0;
            o.y = (c[nt][1] - mu0) * rstd0 * g1 + t1;
            *(float2*)(out0 + col) = o;
        }
        if (act1) {
            float2 o;
            o.x = (c[nt][2] - mu1) * rstd1 * g0 + t0;
            o.y = (c[nt][3] - mu1) * rstd1 * g1 + t1;
            *(float2*)(out1 + col) = o;
        }
    }
}

// ---------------------------------------------------------------------------
extern "C" void kernel_launch(void* const* d_in, const int* in_sizes, int n_in,
                              void* d_out, int out_size) {
    const float* x     = (const float*)d_in[0];
    const int*   ids   = (const int*)d_in[1];   // int32 or int64 (detected on device)
    const float* W     = (const float*)d_in[2];
    const float* bproj = (const float*)d_in[3];
    const float* gamma = (const float*)d_in[4];
    const float* beta  = (const float*)d_in[5];
    float* out  = (float*)d_out;
    float* mask = out + (size_t)BB * TT * DD;

    k_detect<<<1, 256>>>(ids);
    k_prep<<<1, 256>>>(bproj, gamma, beta);
    k_seg<<<BB, 256>>>(ids);
    k_fill<<<(BB * TT) / 32, 256>>>(out, mask);
    k_pool<<<dim3(BB, MAXSEG / 8), 256>>>(x);
    k_gemm<<<dim3(BB, MAXSEG / 32), 256>>>(W, bproj, gamma, beta, out);
}

// round 4
// speedup vs baseline: 2.0288x; 1.0760x over previous
#include <cuda_runtime.h>
#include <cuda_bf16.h>

#define BB 16
#define TT 8192
#define DD 256
#define MAXSEG 4096
#define LN_EPS 1e-5f

// Scratch (static device globals; no runtime allocation)
__device__ int   g_seg_start[BB * MAXSEG];
__device__ int   g_seg_end[BB * MAXSEG];
__device__ int   g_nsegs[BB];
__device__ float g_empty[DD];   // LN(b_proj)*gamma+beta for empty slots

// Dynamic smem layout for k_main (bytes)
#define ASF_PITCH 260                       // fp32 words; 260%32==4 -> conflict-free frag reads
#define OFF_ASF 0                           // 32*260*4 = 33280
#define OFF_BS  33280                       // 256*36*4 = 36864
#define OFF_BP  (33280 + 36864)             // 70144
#define OFF_GM  (OFF_BP + 1024)
#define OFF_BT  (OFF_GM + 1024)
#define OFF_ES  (OFF_BT + 1024)
#define OFF_RS  (OFF_ES + 1024)             // rowsum 32*4*4 = 512
#define OFF_RQ  (OFF_RS + 512)
#define SMEM_TOTAL (OFF_RQ + 512)           // 75776 B

__device__ __forceinline__ unsigned f2tf(float f) {
    unsigned u;
    asm("cvt.rna.tf32.f32 %0, %1;" : "=r"(u) : "f"(f));
    return u;
}

// ---------------------------------------------------------------------------
// Kernel 0: init. Blocks 0..15: detect id width + segment batch b.
//           Block 16: g_empty = LN(b_proj)*gamma+beta.
// ---------------------------------------------------------------------------
__global__ void k_init(const int* __restrict__ ids,
                       const float* __restrict__ bp,
                       const float* __restrict__ gamma,
                       const float* __restrict__ beta) {
    int tid = threadIdx.x;

    if (blockIdx.x == 16) {
        // prep: LN of b_proj
        __shared__ float red[256];
        float v = bp[tid];
        red[tid] = v;
        __syncthreads();
        for (int s = 128; s > 0; s >>= 1) {
            if (tid < s) red[tid] += red[tid + s];
            __syncthreads();
        }
        float mu = red[0] * (1.0f / DD);
        __syncthreads();
        float d = v - mu;
        red[tid] = d * d;
        __syncthreads();
        for (int s = 128; s > 0; s >>= 1) {
            if (tid < s) red[tid] += red[tid + s];
            __syncthreads();
        }
        float var = red[0] * (1.0f / DD);
        g_empty[tid] = d * rsqrtf(var + LN_EPS) * gamma[tid] + beta[tid];
        return;
    }

    int b = blockIdx.x;

    // --- id-width detection (probe first 512 words: safe for both widths;
    //     int64 values in [0,8) -> all odd words zero; int32 random -> not) ---
    __shared__ int any;
    if (tid == 0) any = 0;
    __syncthreads();
    if (ids[2 * tid + 1] != 0) atomicOr(&any, 1);
    __syncthreads();
    int stride = any ? 1 : 2;
    const int* row = ids + (size_t)b * TT * stride;

    // --- segmentation: maximal runs of non-boundary tokens ---
    __shared__ int wts[8], wte[8], wos[8], woe[8];
    int warp = tid >> 5, lane = tid & 31;
    int base = tid * 32;

    int cs = 0, ce = 0;
    bool prevb = (base == 0) || (row[(size_t)(base - 1) * stride] == 0);
    #pragma unroll
    for (int i = 0; i < 32; i++) {
        int t = base + i;
        bool isb = (row[(size_t)t * stride] == 0);
        bool nextb = (t == TT - 1) || (row[(size_t)(t + 1) * stride] == 0);
        cs += (!isb && prevb) ? 1 : 0;
        ce += (!isb && nextb) ? 1 : 0;
        prevb = isb;
    }
    // warp inclusive scan of cs, ce
    int vs = cs, ve = ce;
    #pragma unroll
    for (int off = 1; off < 32; off <<= 1) {
        int ns_ = __shfl_up_sync(0xFFFFFFFFu, vs, off);
        int ne_ = __shfl_up_sync(0xFFFFFFFFu, ve, off);
        if (lane >= off) { vs += ns_; ve += ne_; }
    }
    if (lane == 31) { wts[warp] = vs; wte[warp] = ve; }
    __syncthreads();
    if (tid == 0) {
        int a = 0, c2 = 0;
        #pragma unroll
        for (int i = 0; i < 8; i++) {
            int t1 = wts[i]; wos[i] = a;  a  += t1;
            int t2 = wte[i]; woe[i] = c2; c2 += t2;
        }
        g_nsegs[b] = a;
    }
    __syncthreads();
    int so = (vs - cs) + wos[warp];
    int eo = (ve - ce) + woe[warp];

    prevb = (base == 0) || (row[(size_t)(base - 1) * stride] == 0);
    #pragma unroll
    for (int i = 0; i < 32; i++) {
        int t = base + i;
        bool isb = (row[(size_t)t * stride] == 0);
        bool nextb = (t == TT - 1) || (row[(size_t)(t + 1) * stride] == 0);
        if (!isb && prevb) g_seg_start[b * MAXSEG + (so++)] = t;
        if (!isb && nextb) g_seg_end[b * MAXSEG + (eo++)] = t;
        prevb = isb;
    }
}

// ---------------------------------------------------------------------------
// Kernel 1: fused pool + tf32 GEMM + LN + empty-fill + mask.
// Block = (batch b, 32 output slots m0..m0+31).
//   fully-empty block -> fast fill path.
//   active block      -> pool segments into smem, MMA vs W, LN, scatter;
//                        inactive tail rows get the empty vector.
// ---------------------------------------------------------------------------
__global__ void __launch_bounds__(256) k_main(const float* __restrict__ x,
                                              const float* __restrict__ W,
                                              const float* __restrict__ bproj,
                                              const float* __restrict__ gamma,
                                              const float* __restrict__ beta,
                                              float* __restrict__ out,
                                              float* __restrict__ mask) {
    int b = blockIdx.x;
    int m0 = blockIdx.y * 32;
    int ns = g_nsegs[b];
    int tid = threadIdx.x;
    int warp = tid >> 5, lane = tid & 31;

    // mask for this block's 32 slots
    if (tid < 32) mask[b * TT + m0 + tid] = (m0 + tid < ns) ? 1.0f : 0.0f;

    if (m0 >= ns) {
        // ---- fast path: all 32 rows empty ----
        float4 e0 = *(const float4*)(g_empty + lane * 4);
        float4 e1 = *(const float4*)(g_empty + 128 + lane * 4);
        int row0 = b * TT + m0 + warp * 4;
        #pragma unroll
        for (int i = 0; i < 4; i++) {
            float4* o = (float4*)(out + (size_t)(row0 + i) * DD);
            o[lane] = e0;
            o[32 + lane] = e1;
        }
        return;
    }

    int active = min(32, ns - m0);

    extern __shared__ char sm_raw[];
    float*    AsF = (float*)(sm_raw + OFF_ASF);       // [32][260] pooled means fp32
    unsigned* Bs  = (unsigned*)(sm_raw + OFF_BS);     // [256][36] W chunk tf32
    float*    bpS = (float*)(sm_raw + OFF_BP);
    float*    gmS = (float*)(sm_raw + OFF_GM);
    float*    btS = (float*)(sm_raw + OFF_BT);
    float*    eS  = (float*)(sm_raw + OFF_ES);
    float*    rowsum = (float*)(sm_raw + OFF_RS);     // [32][4]
    float*    rowsq  = (float*)(sm_raw + OFF_RQ);     // [32][4]

    bpS[tid] = bproj[tid];
    gmS[tid] = gamma[tid];
    btS[tid] = beta[tid];
    eS[tid]  = g_empty[tid];

    // ---- pool: warp w handles segments w*4 .. w*4+3 ----
    const float* xb = x + (size_t)b * TT * DD;
    #pragma unroll
    for (int i = 0; i < 4; i++) {
        int sidx = warp * 4 + i;
        if (sidx >= active) break;
        int s = g_seg_start[b * MAXSEG + m0 + sidx];
        int e = g_seg_end[b * MAXSEG + m0 + sidx];
        float4 a0 = make_float4(0.f, 0.f, 0.f, 0.f);
        float4 a1 = make_float4(0.f, 0.f, 0.f, 0.f);
        #pragma unroll 4
        for (int t = s; t <= e; t++) {
            const float4* p = (const float4*)(xb + (size_t)t * DD);
            float4 v0 = p[lane];
            float4 v1 = p[32 + lane];
            a0.x += v0.x; a0.y += v0.y; a0.z += v0.z; a0.w += v0.w;
            a1.x += v1.x; a1.y += v1.y; a1.z += v1.z; a1.w += v1.w;
        }
        float inv = 1.0f / (float)(e - s + 1);
        a0.x *= inv; a0.y *= inv; a0.z *= inv; a0.w *= inv;
        a1.x *= inv; a1.y *= inv; a1.z *= inv; a1.w *= inv;
        *(float4*)&AsF[sidx * ASF_PITCH + lane * 4]       = a0;
        *(float4*)&AsF[sidx * ASF_PITCH + 128 + lane * 4] = a1;
    }
    __syncthreads();

    // ---- tf32 MMA: 8 warps as 2(m16) x 4(n64); mma.m16n8k8 ----
    int wr = warp & 1;
    int wc = warp >> 1;
    int gid = lane >> 2, tig = lane & 3;

    float c[8][4];
    #pragma unroll
    for (int nt = 0; nt < 8; nt++)
        #pragma unroll
        for (int j = 0; j < 4; j++) c[nt][j] = 0.f;

    int lm = tid >> 3;              // 0..31
    int kq = (tid & 7) * 4;         // 0..28

    int ra = wr * 16 + gid;         // A fragment rows
    int rb = ra + 8;

    for (int kt = 0; kt < 8; kt++) {
        int k0 = kt * 32;
        // B chunk 256x32 from W (row n of W is col-major B operand)
        #pragma unroll
        for (int p = 0; p < 8; p++) {
            int e = p * 32 + lm;
            float4 v = *(const float4*)(W + (size_t)e * DD + k0 + kq);
            Bs[e * 36 + kq + 0] = f2tf(v.x);
            Bs[e * 36 + kq + 1] = f2tf(v.y);
            Bs[e * 36 + kq + 2] = f2tf(v.z);
            Bs[e * 36 + kq + 3] = f2tf(v.w);
        }
        __syncthreads();
        #pragma unroll
        for (int ks = 0; ks < 4; ks++) {
            int kk = k0 + ks * 8;
            unsigned a0 = f2tf(AsF[ra * ASF_PITCH + kk + tig]);
            unsigned a1 = f2tf(AsF[rb * ASF_PITCH + kk + tig]);
            unsigned a2 = f2tf(AsF[ra * ASF_PITCH + kk + tig + 4]);
            unsigned a3 = f2tf(AsF[rb * ASF_PITCH + kk + tig + 4]);
            int kc = ks * 8;
            #pragma unroll
            for (int nt = 0; nt < 8; nt++) {
                int n = wc * 64 + nt * 8;
                unsigned b0 = Bs[(n + gid) * 36 + kc + tig];
                unsigned b1 = Bs[(n + gid) * 36 + kc + tig + 4];
                asm volatile(
                    "mma.sync.aligned.m16n8k8.row.col.f32.tf32.tf32.f32 "
                    "{%0,%1,%2,%3}, {%4,%5,%6,%7}, {%8,%9}, {%0,%1,%2,%3};"
                    : "+f"(c[nt][0]), "+f"(c[nt][1]), "+f"(c[nt][2]), "+f"(c[nt][3])
                    : "r"(a0), "r"(a1), "r"(a2), "r"(a3), "r"(b0), "r"(b1));
            }
        }
        __syncthreads();
    }

    // ---- epilogue: +bias, LN per row; inactive rows -> empty vector ----
    float s0 = 0.f, q0 = 0.f, s1 = 0.f, q1 = 0.f;
    #pragma unroll
    for (int nt = 0; nt < 8; nt++) {
        int col = wc * 64 + nt * 8 + 2 * tig;
        float b0v = bpS[col], b1v = bpS[col + 1];
        c[nt][0] += b0v; c[nt][1] += b1v;
        c[nt][2] += b0v; c[nt][3] += b1v;
        s0 += c[nt][0] + c[nt][1];
        q0 += c[nt][0] * c[nt][0] + c[nt][1] * c[nt][1];
        s1 += c[nt][2] + c[nt][3];
        q1 += c[nt][2] * c[nt][2] + c[nt][3] * c[nt][3];
    }
    #pragma unroll
    for (int off = 1; off <= 2; off <<= 1) {
        s0 += __shfl_xor_sync(0xFFFFFFFFu, s0, off);
        q0 += __shfl_xor_sync(0xFFFFFFFFu, q0, off);
        s1 += __shfl_xor_sync(0xFFFFFFFFu, s1, off);
        q1 += __shfl_xor_sync(0xFFFFFFFFu, q1, off);
    }
    if (tig == 0) {
        rowsum[ra * 4 + wc] = s0;
        rowsq [ra * 4 + wc] = q0;
        rowsum[rb * 4 + wc] = s1;
        rowsq [rb * 4 + wc] = q1;
    }
    __syncthreads();

    float sum0 = rowsum[ra*4+0] + rowsum[ra*4+1] + rowsum[ra*4+2] + rowsum[ra*4+3];
    float sq0  = rowsq [ra*4+0] + rowsq [ra*4+1] + rowsq [ra*4+2] + rowsq [ra*4+3];
    float sum1 = rowsum[rb*4+0] + rowsum[rb*4+1] + rowsum[rb*4+2] + rowsum[rb*4+3];
    float sq1  = rowsq [rb*4+0] + rowsq [rb*4+1] + rowsq [rb*4+2] + rowsq [rb*4+3];
    float mu0 = sum0 * (1.0f / DD);
    float mu1 = sum1 * (1.0f / DD);
    float rstd0 = rsqrtf(sq0 * (1.0f / DD) - mu0 * mu0 + LN_EPS);
    float rstd1 = rsqrtf(sq1 * (1.0f / DD) - mu1 * mu1 + LN_EPS);

    bool act0 = ra < active;
    bool act1 = rb < active;
    float* out0 = out + (size_t)(b * TT + m0 + ra) * DD;
    float* out1 = out + (size_t)(b * TT + m0 + rb) * DD;
    #pragma unroll
    for (int nt = 0; nt < 8; nt++) {
        int col = wc * 64 + nt * 8 + 2 * tig;
        float g0 = gmS[col], g1 = gmS[col + 1];
        float t0 = btS[col], t1 = btS[col + 1];
        float2 o;
        if (act0) {
            o.x = (c[nt][0] - mu0) * rstd0 * g0 + t0;
            o.y = (c[nt][1] - mu0) * rstd0 * g1 + t1;
        } else {
            o.x = eS[col];
            o.y = eS[col + 1];
        }
        *(float2*)(out0 + col) = o;
        if (act1) {
            o.x = (c[nt][2] - mu1) * rstd1 * g0 + t0;
            o.y = (c[nt][3] - mu1) * rstd1 * g1 + t1;
        } else {
            o.x = eS[col];
            o.y = eS[col + 1];
        }
        *(float2*)(out1 + col) = o;
    }
}

// ---------------------------------------------------------------------------
extern "C" void kernel_launch(void* const* d_in, const int* in_sizes, int n_in,
                              void* d_out, int out_size) {
    const float* x     = (const float*)d_in[0];
    const int*   ids   = (const int*)d_in[1];   // int32 or int64 (detected on device)
    const float* W     = (const float*)d_in[2];
    const float* bproj = (const float*)d_in[3];
    const float* gamma = (const float*)d_in[4];
    const float* beta  = (const float*)d_in[5];
    float* out  = (float*)d_out;
    float* mask = out + (size_t)BB * TT * DD;

    cudaFuncSetAttribute(k_main, cudaFuncAttributeMaxDynamicSharedMemorySize, SMEM_TOTAL);
    k_init<<<17, 256>>>(ids, bproj, gamma, beta);
    k_main<<<dim3(BB, MAXSEG / 32), 256, SMEM_TOTAL>>>(x, W, bproj, gamma, beta, out, mask);
}

// round 8
// speedup vs baseline: 3.3352x; 1.6439x over previous
#include <cuda_runtime.h>
#include <cuda_bf16.h>

#define BB 16
#define TT 8192
#define DD 256
#define MAXSEG 4096
#define LN_EPS 1e-5f

// Scratch (static device globals; no runtime allocation)
__device__ int   g_seg_start[BB * MAXSEG];
__device__ int   g_seg_end[BB * MAXSEG];
__device__ int   g_nsegs[BB];
__device__ float g_empty[DD];          // LN(b_proj)*gamma+beta for empty slots
// W pre-converted to tf32 MMA B-fragments. frag (nb,kb): 32 lanes x uint2
//  lane (gid=lane>>2, tig=lane&3): { W[nb*8+gid][kb*8+tig], W[nb*8+gid][kb*8+tig+4] }
__device__ uint2 g_Wfrag[32 * 32 * 32];   // 256 KB, L2-resident

// Dynamic smem layout for k_main (bytes)
#define ASF_PITCH 260                   // words; 260%32==4 -> conflict-free frag reads
#define OFF_ASF 0                       // 32*260*4 = 33280 (tf32 bits)
#define OFF_BP  33280
#define OFF_GM  (OFF_BP + 1024)
#define OFF_BT  (OFF_GM + 1024)
#define OFF_ES  (OFF_BT + 1024)
#define OFF_RS  (OFF_ES + 1024)         // rowsum 32*4*4 = 512
#define OFF_RQ  (OFF_RS + 512)
#define SMEM_TOTAL (OFF_RQ + 512)       // 38400 B

__device__ __forceinline__ unsigned f2tf(float f) {
    unsigned u;
    asm("cvt.rna.tf32.f32 %0, %1;" : "=r"(u) : "f"(f));
    return u;
}

// ---------------------------------------------------------------------------
// Kernel 0: init.
//   blocks 0..15 : detect id width + segment batch b
//   block  16    : g_empty = LN(b_proj)*gamma+beta
//   blocks 17..48: convert W row-block nb=bx-17 into g_Wfrag
// ---------------------------------------------------------------------------
__global__ void k_init(const int* __restrict__ ids,
                       const float* __restrict__ W,
                       const float* __restrict__ bp,
                       const float* __restrict__ gamma,
                       const float* __restrict__ beta) {
    int tid = threadIdx.x;
    int bx = blockIdx.x;

    if (bx >= 17) {
        // ---- W -> tf32 fragment pack ----
        int nb = bx - 17;                 // 0..31
        int warp = tid >> 5, lane = tid & 31;
        int gid = lane >> 2, tig = lane & 3;
        #pragma unroll
        for (int i = 0; i < 4; i++) {
            int kb = warp + i * 8;
            const float* wr_ = W + (size_t)(nb * 8 + gid) * DD + kb * 8;
            uint2 v;
            v.x = f2tf(wr_[tig]);
            v.y = f2tf(wr_[tig + 4]);
            g_Wfrag[(nb * 32 + kb) * 32 + lane] = v;
        }
        return;
    }

    if (bx == 16) {
        // ---- LN of b_proj ----
        __shared__ float red[256];
        float v = bp[tid];
        red[tid] = v;
        __syncthreads();
        for (int s = 128; s > 0; s >>= 1) {
            if (tid < s) red[tid] += red[tid + s];
            __syncthreads();
        }
        float mu = red[0] * (1.0f / DD);
        __syncthreads();
        float d = v - mu;
        red[tid] = d * d;
        __syncthreads();
        for (int s = 128; s > 0; s >>= 1) {
            if (tid < s) red[tid] += red[tid + s];
            __syncthreads();
        }
        float var = red[0] * (1.0f / DD);
        g_empty[tid] = d * rsqrtf(var + LN_EPS) * gamma[tid] + beta[tid];
        return;
    }

    int b = bx;

    // ---- id-width detection ----
    __shared__ int any;
    if (tid == 0) any = 0;
    __syncthreads();
    if (ids[2 * tid + 1] != 0) atomicOr(&any, 1);
    __syncthreads();
    int stride = any ? 1 : 2;
    const int* row = ids + (size_t)b * TT * stride;

    // ---- segmentation: maximal runs of non-boundary tokens ----
    __shared__ int wts[8], wte[8], wos[8], woe[8];
    int warp = tid >> 5, lane = tid & 31;
    int base = tid * 32;

    int cs = 0, ce = 0;
    bool prevb = (base == 0) || (row[(size_t)(base - 1) * stride] == 0);
    #pragma unroll
    for (int i = 0; i < 32; i++) {
        int t = base + i;
        bool isb = (row[(size_t)t * stride] == 0);
        bool nextb = (t == TT - 1) || (row[(size_t)(t + 1) * stride] == 0);
        cs += (!isb && prevb) ? 1 : 0;
        ce += (!isb && nextb) ? 1 : 0;
        prevb = isb;
    }
    int vs = cs, ve = ce;
    #pragma unroll
    for (int off = 1; off < 32; off <<= 1) {
        int ns_ = __shfl_up_sync(0xFFFFFFFFu, vs, off);
        int ne_ = __shfl_up_sync(0xFFFFFFFFu, ve, off);
        if (lane >= off) { vs += ns_; ve += ne_; }
    }
    if (lane == 31) { wts[warp] = vs; wte[warp] = ve; }
    __syncthreads();
    if (tid == 0) {
        int a = 0, c2 = 0;
        #pragma unroll
        for (int i = 0; i < 8; i++) {
            int t1 = wts[i]; wos[i] = a;  a  += t1;
            int t2 = wte[i]; woe[i] = c2; c2 += t2;
        }
        g_nsegs[b] = a;
    }
    __syncthreads();
    int so = (vs - cs) + wos[warp];
    int eo = (ve - ce) + woe[warp];

    prevb = (base == 0) || (row[(size_t)(base - 1) * stride] == 0);
    #pragma unroll
    for (int i = 0; i < 32; i++) {
        int t = base + i;
        bool isb = (row[(size_t)t * stride] == 0);
        bool nextb = (t == TT - 1) || (row[(size_t)(t + 1) * stride] == 0);
        if (!isb && prevb) g_seg_start[b * MAXSEG + (so++)] = t;
        if (!isb && nextb) g_seg_end[b * MAXSEG + (eo++)] = t;
        prevb = isb;
    }
}

// ---------------------------------------------------------------------------
// Kernel 1: fused pool + tf32 GEMM (B frags from L2) + LN + empty-fill + mask.
// ---------------------------------------------------------------------------
__global__ void __launch_bounds__(256) k_main(const float* __restrict__ x,
                                              const float* __restrict__ bproj,
                                              const float* __restrict__ gamma,
                                              const float* __restrict__ beta,
                                              float* __restrict__ out,
                                              float* __restrict__ mask) {
    int b = blockIdx.x;
    int m0 = blockIdx.y * 32;
    int ns = g_nsegs[b];
    int tid = threadIdx.x;
    int warp = tid >> 5, lane = tid & 31;

    if (tid < 32) mask[b * TT + m0 + tid] = (m0 + tid < ns) ? 1.0f : 0.0f;

    if (m0 >= ns) {
        // ---- fast path: all 32 rows empty ----
        float4 e0 = *(const float4*)(g_empty + lane * 4);
        float4 e1 = *(const float4*)(g_empty + 128 + lane * 4);
        int row0 = b * TT + m0 + warp * 4;
        #pragma unroll
        for (int i = 0; i < 4; i++) {
            float4* o = (float4*)(out + (size_t)(row0 + i) * DD);
            o[lane] = e0;
            o[32 + lane] = e1;
        }
        return;
    }

    int active = min(32, ns - m0);

    extern __shared__ char sm_raw[];
    unsigned* AsU = (unsigned*)(sm_raw + OFF_ASF);    // [32][260] pooled means (tf32 bits)
    float*    bpS = (float*)(sm_raw + OFF_BP);
    float*    gmS = (float*)(sm_raw + OFF_GM);
    float*    btS = (float*)(sm_raw + OFF_BT);
    float*    eS  = (float*)(sm_raw + OFF_ES);
    float*    rowsum = (float*)(sm_raw + OFF_RS);     // [32][4]
    float*    rowsq  = (float*)(sm_raw + OFF_RQ);     // [32][4]

    bpS[tid] = bproj[tid];
    gmS[tid] = gamma[tid];
    btS[tid] = beta[tid];
    eS[tid]  = g_empty[tid];

    // ---- pool: warp w handles segments w*4 .. w*4+3 (zeros for inactive) ----
    const float* xb = x + (size_t)b * TT * DD;
    #pragma unroll
    for (int i = 0; i < 4; i++) {
        int sidx = warp * 4 + i;
        uint4 o0 = make_uint4(0u, 0u, 0u, 0u);
        uint4 o1 = make_uint4(0u, 0u, 0u, 0u);
        if (sidx < active) {
            int s = g_seg_start[b * MAXSEG + m0 + sidx];
            int e = g_seg_end[b * MAXSEG + m0 + sidx];
            float4 a0 = make_float4(0.f, 0.f, 0.f, 0.f);
            float4 a1 = make_float4(0.f, 0.f, 0.f, 0.f);
            #pragma unroll 4
            for (int t = s; t <= e; t++) {
                const float4* p = (const float4*)(xb + (size_t)t * DD);
                float4 v0 = p[lane];
                float4 v1 = p[32 + lane];
                a0.x += v0.x; a0.y += v0.y; a0.z += v0.z; a0.w += v0.w;
                a1.x += v1.x; a1.y += v1.y; a1.z += v1.z; a1.w += v1.w;
            }
            float inv = 1.0f / (float)(e - s + 1);
            o0 = make_uint4(f2tf(a0.x * inv), f2tf(a0.y * inv),
                            f2tf(a0.z * inv), f2tf(a0.w * inv));
            o1 = make_uint4(f2tf(a1.x * inv), f2tf(a1.y * inv),
                            f2tf(a1.z * inv), f2tf(a1.w * inv));
        }
        *(uint4*)&AsU[sidx * ASF_PITCH + lane * 4]       = o0;
        *(uint4*)&AsU[sidx * ASF_PITCH + 128 + lane * 4] = o1;
    }
    __syncthreads();

    // ---- tf32 MMA: 8 warps as 2(m16) x 4(n64); B frags via coalesced LDG.64 ----
    int wr = warp & 1;
    int wc = warp >> 1;
    int gid = lane >> 2, tig = lane & 3;

    float c[8][4];
    #pragma unroll
    for (int nt = 0; nt < 8; nt++)
        #pragma unroll
        for (int j = 0; j < 4; j++) c[nt][j] = 0.f;

    int ra = wr * 16 + gid;
    int rb = ra + 8;
    const unsigned* Arow0 = AsU + ra * ASF_PITCH;
    const unsigned* Arow1 = AsU + rb * ASF_PITCH;
    const uint2* Wf = g_Wfrag + ((size_t)(wc * 8) * 32 + 0) * 32 + lane;

    #pragma unroll 4
    for (int k8 = 0; k8 < 32; k8++) {
        int kk = k8 * 8;
        unsigned a0 = Arow0[kk + tig];
        unsigned a1 = Arow1[kk + tig];
        unsigned a2 = Arow0[kk + tig + 4];
        unsigned a3 = Arow1[kk + tig + 4];
        uint2 bf[8];
        #pragma unroll
        for (int nt = 0; nt < 8; nt++)
            bf[nt] = Wf[(size_t)(nt * 32 + k8) * 32];
        #pragma unroll
        for (int nt = 0; nt < 8; nt++) {
            asm volatile(
                "mma.sync.aligned.m16n8k8.row.col.f32.tf32.tf32.f32 "
                "{%0,%1,%2,%3}, {%4,%5,%6,%7}, {%8,%9}, {%0,%1,%2,%3};"
                : "+f"(c[nt][0]), "+f"(c[nt][1]), "+f"(c[nt][2]), "+f"(c[nt][3])
                : "r"(a0), "r"(a1), "r"(a2), "r"(a3), "r"(bf[nt].x), "r"(bf[nt].y));
        }
    }

    // ---- epilogue: +bias, LN per row; inactive rows -> empty vector ----
    float s0 = 0.f, q0 = 0.f, s1 = 0.f, q1 = 0.f;
    #pragma unroll
    for (int nt = 0; nt < 8; nt++) {
        int col = wc * 64 + nt * 8 + 2 * tig;
        float b0v = bpS[col], b1v = bpS[col + 1];
        c[nt][0] += b0v; c[nt][1] += b1v;
        c[nt][2] += b0v; c[nt][3] += b1v;
        s0 += c[nt][0] + c[nt][1];
        q0 += c[nt][0] * c[nt][0] + c[nt][1] * c[nt][1];
        s1 += c[nt][2] + c[nt][3];
        q1 += c[nt][2] * c[nt][2] + c[nt][3] * c[nt][3];
    }
    #pragma unroll
    for (int off = 1; off <= 2; off <<= 1) {
        s0 += __shfl_xor_sync(0xFFFFFFFFu, s0, off);
        q0 += __shfl_xor_sync(0xFFFFFFFFu, q0, off);
        s1 += __shfl_xor_sync(0xFFFFFFFFu, s1, off);
        q1 += __shfl_xor_sync(0xFFFFFFFFu, q1, off);
    }
    if (tig == 0) {
        rowsum[ra * 4 + wc] = s0;
        rowsq [ra * 4 + wc] = q0;
        rowsum[rb * 4 + wc] = s1;
        rowsq [rb * 4 + wc] = q1;
    }
    __syncthreads();

    float sum0 = rowsum[ra*4+0] + rowsum[ra*4+1] + rowsum[ra*4+2] + rowsum[ra*4+3];
    float sq0  = rowsq [ra*4+0] + rowsq [ra*4+1] + rowsq [ra*4+2] + rowsq [ra*4+3];
    float sum1 = rowsum[rb*4+0] + rowsum[rb*4+1] + rowsum[rb*4+2] + rowsum[rb*4+3];
    float sq1  = rowsq [rb*4+0] + rowsq [rb*4+1] + rowsq [rb*4+2] + rowsq [rb*4+3];
    float mu0 = sum0 * (1.0f / DD);
    float mu1 = sum1 * (1.0f / DD);
    float rstd0 = rsqrtf(sq0 * (1.0f / DD) - mu0 * mu0 + LN_EPS);
    float rstd1 = rsqrtf(sq1 * (1.0f / DD) - mu1 * mu1 + LN_EPS);

    bool act0 = ra < active;
    bool act1 = rb < active;
    float* out0 = out + (size_t)(b * TT + m0 + ra) * DD;
    float* out1 = out + (size_t)(b * TT + m0 + rb) * DD;
    #pragma unroll
    for (int nt = 0; nt < 8; nt++) {
        int col = wc * 64 + nt * 8 + 2 * tig;
        float g0 = gmS[col], g1 = gmS[col + 1];
        float t0 = btS[col], t1 = btS[col + 1];
        float2 o;
        if (act0) {
            o.x = (c[nt][0] - mu0) * rstd0 * g0 + t0;
            o.y = (c[nt][1] - mu0) * rstd0 * g1 + t1;
        } else {
            o.x = eS[col];
            o.y = eS[col + 1];
        }
        *(float2*)(out0 + col) = o;
        if (act1) {
            o.x = (c[nt][2] - mu1) * rstd1 * g0 + t0;
            o.y = (c[nt][3] - mu1) * rstd1 * g1 + t1;
        } else {
            o.x = eS[col];
            o.y = eS[col + 1];
        }
        *(float2*)(out1 + col) = o;
    }
}

// ---------------------------------------------------------------------------
extern "C" void kernel_launch(void* const* d_in, const int* in_sizes, int n_in,
                              void* d_out, int out_size) {
    const float* x     = (const float*)d_in[0];
    const int*   ids   = (const int*)d_in[1];   // int32 or int64 (detected on device)
    const float* W     = (const float*)d_in[2];
    const float* bproj = (const float*)d_in[3];
    const float* gamma = (const float*)d_in[4];
    const float* beta  = (const float*)d_in[5];
    float* out  = (float*)d_out;
    float* mask = out + (size_t)BB * TT * DD;

    cudaFuncSetAttribute(k_main, cudaFuncAttributeMaxDynamicSharedMemorySize, SMEM_TOTAL);
    k_init<<<49, 256>>>(ids, W, bproj, gamma, beta);
    k_main<<<dim3(BB, MAXSEG / 32), 256, SMEM_TOTAL>>>(x, bproj, gamma, beta, out, mask);
}